// round 10
// baseline (speedup 1.0000x reference)
#include <cuda_runtime.h>
#include <cuda_bf16.h>
#include <cstdint>

#define B_  2
#define T_  2048
#define C_  768
#define H_  12
#define D_  64
#define HD_ 768
#define W3_ 2304   // 3*HD
#define CH_ 64
#define CL_ (T_/CH_)   // 32

typedef unsigned long long u64;

// ---- packed f32x2 helpers -------------------------------------------------
__device__ __forceinline__ u64 pk2(float lo, float hi) {
    u64 r; asm("mov.b64 %0,{%1,%2};" : "=l"(r) : "f"(lo), "f"(hi)); return r;
}
__device__ __forceinline__ u64 dup2(float v) { return pk2(v, v); }
__device__ __forceinline__ float2 up2(u64 v) {
    float2 r; asm("mov.b64 {%0,%1},%2;" : "=f"(r.x), "=f"(r.y) : "l"(v)); return r;
}
__device__ __forceinline__ void fma2(u64& d, u64 a, u64 b) {
    asm("fma.rn.f32x2 %0,%1,%2,%3;" : "=l"(d) : "l"(a), "l"(b), "l"(d));
}

// ---- tf32 / fast-math helpers ----------------------------------------------
__device__ __forceinline__ uint32_t tf32r(float x) {
    uint32_t r; asm("cvt.rna.tf32.f32 %0,%1;" : "=r"(r) : "f"(x)); return r;
}
__device__ __forceinline__ float ex2(float x) {
    float r; asm("ex2.approx.ftz.f32 %0,%1;" : "=f"(r) : "f"(x)); return r;
}
__device__ __forceinline__ float frcp(float x) {
    float r; asm("rcp.approx.ftz.f32 %0,%1;" : "=f"(r) : "f"(x)); return r;
}
#define MMA_TF32(c,a,b0,b1) \
    asm volatile("mma.sync.aligned.m16n8k8.row.col.f32.tf32.tf32.f32 " \
        "{%0,%1,%2,%3},{%4,%5,%6,%7},{%8,%9},{%0,%1,%2,%3};" \
        : "+f"((c)[0]),"+f"((c)[1]),"+f"((c)[2]),"+f"((c)[3]) \
        : "r"((a)[0]),"r"((a)[1]),"r"((a)[2]),"r"((a)[3]),"r"(b0),"r"(b1))

// Scratch
__device__ float g_qkv[(size_t)B_ * T_ * W3_];
__device__ float g_ff [(size_t)B_ * T_ * T_];
__device__ float g_ffsum[B_ * T_];
__device__ float g_att[(size_t)B_ * T_ * HD_];
__device__ float g_csum[B_ * CH_ * T_];

// ---------------------------------------------------------------------------
// Fused QKV GEMM: bulk tf32 tiles (grid.x < 18) + exact fp32 patch blocks
// (grid.x 18,19) recomputing head-0 q/k columns. Bulk skips stores to the
// patch column ranges to avoid write races.
// ---------------------------------------------------------------------------
#define AST 20
#define BST 136
__global__ __launch_bounds__(256) void qkv_fused(
    const float* __restrict__ A, const float* __restrict__ Bm,
    const float* __restrict__ bias, float* __restrict__ Cm,
    int M, int N, int K)
{
    __shared__ float As[128 * AST];
    __shared__ float Bs[16 * BST];
    int tid = threadIdx.x, lane = tid & 31, w = tid >> 5;

    if (blockIdx.x >= (unsigned)(N / 128)) {
        // ---------------- exact fp32 patch (head-0 q,k columns) ----------
        float (*pAs)[68] = (float(*)[68])As;
        float (*pBs)[68] = (float(*)[68])Bs;
        int tx = tid & 15, ty = tid >> 4;
        int colbase = (blockIdx.x - N / 128) * 768;   // 0 or 768
        int arow = tid >> 2, acol = (tid & 3) * 4;
        int brow = tid >> 4, bcol = (tid & 15) * 4;

#pragma unroll 1
        for (int sub = 0; sub < 2; sub++) {
            int row0 = blockIdx.y * 128 + sub * 64;
            const float* Ap = A + (size_t)(row0 + arow) * K + acol;
            const float* Bp = Bm + (size_t)brow * N + colbase + bcol;

            u64 acc[4][2];
#pragma unroll
            for (int i = 0; i < 4; i++) { acc[i][0] = 0ull; acc[i][1] = 0ull; }

            for (int k0 = 0; k0 < K; k0 += 16) {
                float4 a = *(const float4*)(Ap + k0);
                float4 b = *(const float4*)(Bp + (size_t)k0 * N);
                __syncthreads();
                pAs[acol + 0][arow] = a.x; pAs[acol + 1][arow] = a.y;
                pAs[acol + 2][arow] = a.z; pAs[acol + 3][arow] = a.w;
                *(float4*)&pBs[brow][bcol] = b;
                __syncthreads();
#pragma unroll
                for (int kk = 0; kk < 16; kk++) {
                    float4 av = *(const float4*)&pAs[kk][ty * 4];
                    u64 ad[4];
                    ad[0] = dup2(av.x); ad[1] = dup2(av.y);
                    ad[2] = dup2(av.z); ad[3] = dup2(av.w);
                    u64 bx0 = *(const u64*)&pBs[kk][tx * 4];
                    u64 bx1 = *(const u64*)&pBs[kk][tx * 4 + 2];
#pragma unroll
                    for (int i = 0; i < 4; i++) {
                        fma2(acc[i][0], ad[i], bx0);
                        fma2(acc[i][1], ad[i], bx1);
                    }
                }
            }
#pragma unroll
            for (int i = 0; i < 4; i++) {
                int r = row0 + ty * 4 + i;
                int cc = colbase + tx * 4;
                float2 p0 = up2(acc[i][0]);
                float2 p1 = up2(acc[i][1]);
                float4 o;
                o.x = p0.x + bias[cc + 0];
                o.y = p0.y + bias[cc + 1];
                o.z = p1.x + bias[cc + 2];
                o.w = p1.y + bias[cc + 3];
                *(float4*)&Cm[(size_t)r * N + cc] = o;
            }
        }
        return;
    }

    // ---------------- bulk tf32 tensor-core GEMM -------------------------
    int gid = lane >> 2, tig = lane & 3;
    int row0 = blockIdx.y * 128, col0 = blockIdx.x * 128;

    int arow = tid >> 1, acol = (tid & 1) * 8;
    int brow = tid >> 4, bcol = (tid & 15) * 8;
    const float* Ap = A + (size_t)(row0 + arow) * K + acol;
    const float* Bp = Bm + (size_t)brow * N + col0 + bcol;

    float c[16][4];
#pragma unroll
    for (int g = 0; g < 16; g++)
#pragma unroll
        for (int j = 0; j < 4; j++) c[g][j] = 0.f;

    float4 a0 = *(const float4*)(Ap);
    float4 a1 = *(const float4*)(Ap + 4);
    float4 b0 = *(const float4*)(Bp);
    float4 b1 = *(const float4*)(Bp + 4);

    for (int k0 = 0; k0 < K; k0 += 16) {
        __syncthreads();
        {
            float* ad = As + arow * AST + acol;
            ad[0] = __uint_as_float(tf32r(a0.x));
            ad[1] = __uint_as_float(tf32r(a0.y));
            ad[2] = __uint_as_float(tf32r(a0.z));
            ad[3] = __uint_as_float(tf32r(a0.w));
            ad[4] = __uint_as_float(tf32r(a1.x));
            ad[5] = __uint_as_float(tf32r(a1.y));
            ad[6] = __uint_as_float(tf32r(a1.z));
            ad[7] = __uint_as_float(tf32r(a1.w));
            float* bd = Bs + brow * BST + bcol;
            bd[0] = __uint_as_float(tf32r(b0.x));
            bd[1] = __uint_as_float(tf32r(b0.y));
            bd[2] = __uint_as_float(tf32r(b0.z));
            bd[3] = __uint_as_float(tf32r(b0.w));
            bd[4] = __uint_as_float(tf32r(b1.x));
            bd[5] = __uint_as_float(tf32r(b1.y));
            bd[6] = __uint_as_float(tf32r(b1.z));
            bd[7] = __uint_as_float(tf32r(b1.w));
        }
        __syncthreads();
        if (k0 + 16 < K) {
            a0 = *(const float4*)(Ap + k0 + 16);
            a1 = *(const float4*)(Ap + k0 + 20);
            b0 = *(const float4*)(Bp + (size_t)(k0 + 16) * N);
            b1 = *(const float4*)(Bp + (size_t)(k0 + 16) * N + 4);
        }
#pragma unroll
        for (int kc = 0; kc < 2; kc++) {
            uint32_t af[4];
            const float* ab = As + (16 * w + gid) * AST + kc * 8 + tig;
            af[0] = __float_as_uint(ab[0]);
            af[1] = __float_as_uint(ab[8 * AST]);
            af[2] = __float_as_uint(ab[4]);
            af[3] = __float_as_uint(ab[8 * AST + 4]);
            const float* bb = Bs + (kc * 8 + tig) * BST + gid;
#pragma unroll
            for (int g = 0; g < 16; g++) {
                uint32_t bf0 = __float_as_uint(bb[g * 8]);
                uint32_t bf1 = __float_as_uint(bb[4 * BST + g * 8]);
                MMA_TF32(c[g], af, bf0, bf1);
            }
        }
    }

    int crow = row0 + 16 * w + gid;
#pragma unroll
    for (int g = 0; g < 16; g++) {
        int cc = col0 + g * 8 + 2 * tig;
        bool skip = (cc < 64) || (cc >= 768 && cc < 832);   // patch-owned cols
        if (skip) continue;
        float bx0 = bias[cc], bx1 = bias[cc + 1];
        float2 w0 = make_float2(c[g][0] + bx0, c[g][1] + bx1);
        float2 w1 = make_float2(c[g][2] + bx0, c[g][3] + bx1);
        *(float2*)&Cm[(size_t)crow * N + cc] = w0;
        *(float2*)&Cm[(size_t)(crow + 8) * N + cc] = w1;
    }
}

// ---------------------------------------------------------------------------
// Plain tf32 GEMM (proj) — unchanged R8 version.
// ---------------------------------------------------------------------------
__global__ __launch_bounds__(256) void sgemm_tf32(
    const float* __restrict__ A, const float* __restrict__ Bm,
    const float* __restrict__ bias, float* __restrict__ Cm,
    int M, int N, int K)
{
    __shared__ float As[128 * AST];
    __shared__ float Bs[16 * BST];
    int tid = threadIdx.x, lane = tid & 31, w = tid >> 5;
    int gid = lane >> 2, tig = lane & 3;
    int row0 = blockIdx.y * 128, col0 = blockIdx.x * 128;

    int arow = tid >> 1, acol = (tid & 1) * 8;
    int brow = tid >> 4, bcol = (tid & 15) * 8;
    const float* Ap = A + (size_t)(row0 + arow) * K + acol;
    const float* Bp = Bm + (size_t)brow * N + col0 + bcol;

    float c[16][4];
#pragma unroll
    for (int g = 0; g < 16; g++)
#pragma unroll
        for (int j = 0; j < 4; j++) c[g][j] = 0.f;

    float4 a0 = *(const float4*)(Ap);
    float4 a1 = *(const float4*)(Ap + 4);
    float4 b0 = *(const float4*)(Bp);
    float4 b1 = *(const float4*)(Bp + 4);

    for (int k0 = 0; k0 < K; k0 += 16) {
        __syncthreads();
        {
            float* ad = As + arow * AST + acol;
            ad[0] = __uint_as_float(tf32r(a0.x));
            ad[1] = __uint_as_float(tf32r(a0.y));
            ad[2] = __uint_as_float(tf32r(a0.z));
            ad[3] = __uint_as_float(tf32r(a0.w));
            ad[4] = __uint_as_float(tf32r(a1.x));
            ad[5] = __uint_as_float(tf32r(a1.y));
            ad[6] = __uint_as_float(tf32r(a1.z));
            ad[7] = __uint_as_float(tf32r(a1.w));
            float* bd = Bs + brow * BST + bcol;
            bd[0] = __uint_as_float(tf32r(b0.x));
            bd[1] = __uint_as_float(tf32r(b0.y));
            bd[2] = __uint_as_float(tf32r(b0.z));
            bd[3] = __uint_as_float(tf32r(b0.w));
            bd[4] = __uint_as_float(tf32r(b1.x));
            bd[5] = __uint_as_float(tf32r(b1.y));
            bd[6] = __uint_as_float(tf32r(b1.z));
            bd[7] = __uint_as_float(tf32r(b1.w));
        }
        __syncthreads();
        if (k0 + 16 < K) {
            a0 = *(const float4*)(Ap + k0 + 16);
            a1 = *(const float4*)(Ap + k0 + 20);
            b0 = *(const float4*)(Bp + (size_t)(k0 + 16) * N);
            b1 = *(const float4*)(Bp + (size_t)(k0 + 16) * N + 4);
        }
#pragma unroll
        for (int kc = 0; kc < 2; kc++) {
            uint32_t af[4];
            const float* ab = As + (16 * w + gid) * AST + kc * 8 + tig;
            af[0] = __float_as_uint(ab[0]);
            af[1] = __float_as_uint(ab[8 * AST]);
            af[2] = __float_as_uint(ab[4]);
            af[3] = __float_as_uint(ab[8 * AST + 4]);
            const float* bb = Bs + (kc * 8 + tig) * BST + gid;
#pragma unroll
            for (int g = 0; g < 16; g++) {
                uint32_t bf0 = __float_as_uint(bb[g * 8]);
                uint32_t bf1 = __float_as_uint(bb[4 * BST + g * 8]);
                MMA_TF32(c[g], af, bf0, bf1);
            }
        }
    }

    int crow = row0 + 16 * w + gid;
#pragma unroll
    for (int g = 0; g < 16; g++) {
        int cc = col0 + g * 8 + 2 * tig;
        float bx0 = bias[cc], bx1 = bias[cc + 1];
        float2 w0 = make_float2(c[g][0] + bx0, c[g][1] + bx1);
        float2 w1 = make_float2(c[g][2] + bx0, c[g][3] + bx1);
        *(float2*)&Cm[(size_t)crow * N + cc] = w0;
        *(float2*)&Cm[(size_t)(crow + 8) * N + cc] = w1;
    }
}

// ---------------------------------------------------------------------------
// Head-0 scores FUSED with cumsum pass1: each lower-tri 64x64 tile computes
// masked S, writes it, and reduces its per-column sums into the two 32-row
// chunks it owns (same ascending row order as old pass1 -> bit-identical).
// ---------------------------------------------------------------------------
__global__ __launch_bounds__(256) void scores_csum(
    const float* __restrict__ qkv, float* __restrict__ S)
{
    int b = blockIdx.z, tb = blockIdx.y, sb = blockIdx.x;
    int t0 = tb * 64, s0 = sb * 64;
    if (s0 > t0) return;                      // upper tiles: csum stays 0
    int tid = threadIdx.x, tx = tid & 15, ty = tid >> 4;
    float* Sb = S + (size_t)b * T_ * T_;

    __shared__ float Qs[64][68];
    __shared__ float Ks[64][68];
    __shared__ float red[64][17];
    const float* qb = qkv + ((size_t)b * T_ + t0) * W3_;
    const float* kb = qkv + ((size_t)b * T_ + s0) * W3_ + HD_;
    int lr = tid >> 4, lc = (tid & 15) * 4;
#pragma unroll
    for (int g = 0; g < 4; g++) {
        int r = lr + g * 16;
        *(float4*)&Qs[r][lc] = *(const float4*)&qb[(size_t)r * W3_ + lc];
        *(float4*)&Ks[r][lc] = *(const float4*)&kb[(size_t)r * W3_ + lc];
    }
    __syncthreads();

    float acc[4][4] = {};
#pragma unroll
    for (int dk = 0; dk < 16; dk++) {
        float4 qv[4], kv[4];
#pragma unroll
        for (int i = 0; i < 4; i++) qv[i] = *(const float4*)&Qs[ty * 4 + i][dk * 4];
#pragma unroll
        for (int j = 0; j < 4; j++) kv[j] = *(const float4*)&Ks[tx * 4 + j][dk * 4];
#pragma unroll
        for (int i = 0; i < 4; i++)
#pragma unroll
            for (int j = 0; j < 4; j++)
                acc[i][j] += qv[i].x * kv[j].x + qv[i].y * kv[j].y
                           + qv[i].z * kv[j].z + qv[i].w * kv[j].w;
    }

    float colsum[4] = {0.f, 0.f, 0.f, 0.f};
#pragma unroll
    for (int i = 0; i < 4; i++) {
        int t = t0 + ty * 4 + i;
        float out[4];
#pragma unroll
        for (int j = 0; j < 4; j++) {
            int s = s0 + tx * 4 + j;
            float v = acc[i][j] * 0.125f;
            out[j] = (s < t && s > 0) ? fmaxf(v, 0.f) : 0.f;
            colsum[j] += out[j];
        }
        *(float4*)&Sb[(size_t)t * T_ + s0 + tx * 4] = *(float4*)out;
    }
#pragma unroll
    for (int j = 0; j < 4; j++) red[tx * 4 + j][ty] = colsum[j];
    __syncthreads();

    if (tid < 128) {
        int col = tid & 63, half = tid >> 6;
        float s = 0.f;
#pragma unroll
        for (int k = 0; k < 8; k++) s += red[col][half * 8 + k];
        int chunk = tb * 2 + half;            // CL_=32: tile spans 2 chunks
        g_csum[(b * CH_ + chunk) * T_ + s0 + col] = s;
    }
}

// ---------------------------------------------------------------------------
// Cumsum pass2 (unchanged).
// ---------------------------------------------------------------------------
__global__ __launch_bounds__(256) void cumsum_pass2(float* __restrict__ S)
{
    int b = blockIdx.y, chunk = blockIdx.z;
    int c0 = chunk * CL_;
    int s0 = blockIdx.x * 256;
    if (s0 >= c0 + CL_) return;
    int s = s0 + threadIdx.x;
    float base = 0.f;
    for (int c = 0; c < chunk; c++) base += g_csum[(b * CH_ + c) * T_ + s];
    float* p = S + (size_t)b * T_ * T_ + (size_t)c0 * T_ + s;
    float acc = base;
#pragma unroll 8
    for (int t = 0; t < CL_; t++) {
        float v = p[(size_t)t * T_];
        p[(size_t)t * T_] = acc;
        acc += (c0 + t > s) ? v : 0.f;
    }
}

// ---------------------------------------------------------------------------
__global__ __launch_bounds__(256) void ffsum_kernel(const float* __restrict__ FF)
{
    int b = blockIdx.y, t = blockIdx.x;
    const float4* row = (const float4*)(FF + ((size_t)b * T_ + t) * T_);
    int n4 = (t >> 2) + 1;
    float s = 0.f;
    for (int j = threadIdx.x; j < n4; j += 256) {
        float4 v = row[j];
        int sb = j * 4;
        s += (sb     <= t ? fminf(v.x, 1.f) : 0.f)
           + (sb + 1 <= t ? fminf(v.y, 1.f) : 0.f)
           + (sb + 2 <= t ? fminf(v.z, 1.f) : 0.f)
           + (sb + 3 <= t ? fminf(v.w, 1.f) : 0.f);
    }
#pragma unroll
    for (int off = 16; off; off >>= 1) s += __shfl_xor_sync(0xffffffffu, s, off);
    __shared__ float red[8];
    int lane = threadIdx.x & 31, w = threadIdx.x >> 5;
    if (lane == 0) red[w] = s;
    __syncthreads();
    if (w == 0) {
        s = (lane < 8) ? red[lane] : 0.f;
#pragma unroll
        for (int off = 4; off; off >>= 1) s += __shfl_xor_sync(0xffffffffu, s, off);
        if (lane == 0) g_ffsum[b * T_ + t] = s;
    }
}

__global__ __launch_bounds__(256) void m_kernel(float* __restrict__ Mout)
{
    size_t idx4 = (size_t)blockIdx.x * 256 + threadIdx.x;
    size_t idx = idx4 * 4;
    int j = (int)(idx % T_);
    size_t r = idx / T_;
    int i = (int)(r % T_);
    int b = (int)(r / T_);
    float4 fs = *(const float4*)&g_ffsum[b * T_ + j];
    float fi = (float)i;
    float4 o = make_float4(fi - fs.x, fi - fs.y, fi - fs.z, fi - fs.w);
    *(float4*)&Mout[idx] = o;
}

// ---------------------------------------------------------------------------
// Flash attention — exact R8 (602us) version.
// ---------------------------------------------------------------------------
#define FSTQ 68
#define FSTV 72
#define QOF 0
#define KOF (128 * FSTQ)
#define VOF (KOF + 64 * FSTQ)
#define FSMEM ((128 * FSTQ + 64 * FSTQ + 64 * FSTV) * 4)   // 70656 B
#define L2E 1.44269504f

__device__ __forceinline__ uint4 cvt4(float4 v) {
    uint4 r;
    r.x = tf32r(v.x); r.y = tf32r(v.y); r.z = tf32r(v.z); r.w = tf32r(v.w);
    return r;
}

__global__ __launch_bounds__(128) void flash_tf32(
    const float* __restrict__ qkv, const float* __restrict__ FF,
    float* __restrict__ Y)
{
    extern __shared__ __align__(16) float sm[];

    int tid = threadIdx.x;
    int lane = tid & 31, w = tid >> 5;
    int gid = lane >> 2, tig = lane & 3;
    int tb = gridDim.x - 1 - blockIdx.x;
    int bh = blockIdx.y;
    int b = bh / H_, h = bh % H_;
    int t0 = tb * 128;

    const float* kvb = qkv + (size_t)b * T_ * W3_;

    {
        const float* qp = kvb + (size_t)(t0 + tid) * W3_ + h * D_;
        uint4* dst = (uint4*)(sm + QOF + tid * FSTQ);
#pragma unroll
        for (int u = 0; u < 16; u++)
            dst[u] = cvt4(*(const float4*)(qp + u * 4));
    }
    __syncthreads();

    uint32_t aq[2][8][4];
#pragma unroll
    for (int mt = 0; mt < 2; mt++)
#pragma unroll
        for (int kc = 0; kc < 8; kc++) {
            const float* q0 = sm + QOF + (32 * w + 16 * mt + gid) * FSTQ + kc * 8 + tig;
            aq[mt][kc][0] = __float_as_uint(q0[0]);
            aq[mt][kc][1] = __float_as_uint(q0[8 * FSTQ]);
            aq[mt][kc][2] = __float_as_uint(q0[4]);
            aq[mt][kc][3] = __float_as_uint(q0[8 * FSTQ + 4]);
        }

    float mrow[2][2], lrow[2][2];
    float o[2][8][4];
#pragma unroll
    for (int mt = 0; mt < 2; mt++) {
        mrow[mt][0] = -1e30f; mrow[mt][1] = -1e30f;
        lrow[mt][0] = 0.f;    lrow[mt][1] = 0.f;
#pragma unroll
        for (int dg = 0; dg < 8; dg++)
#pragma unroll
            for (int j = 0; j < 4; j++) o[mt][dg][j] = 0.f;
    }

    int qr[2] = { t0 + 32 * w + gid, t0 + 32 * w + 16 + gid };
    const float* ffb = FF + (size_t)b * T_ * T_;
    int cl = tig << 1;
    int src0 = (lane & ~3) | (tig >> 1);
    int src1 = src0 + 2;
    bool od = (tig & 1);

    int nkb = 2 * tb + 2;
    for (int kb = 0; kb < nkb; kb++) {
        int s0 = kb * 64;
        __syncthreads();
        {
            int r = tid >> 1, c0 = (tid & 1) * 32;
            const float* kp = kvb + (size_t)(s0 + r) * W3_ + HD_     + h * D_ + c0;
            const float* vp = kvb + (size_t)(s0 + r) * W3_ + 2 * HD_ + h * D_ + c0;
            uint4* dk = (uint4*)(sm + KOF + r * FSTQ + c0);
            uint4* dv = (uint4*)(sm + VOF + r * FSTV + c0);
#pragma unroll
            for (int u = 0; u < 8; u++) {
                dk[u] = cvt4(*(const float4*)(kp + u * 4));
                dv[u] = cvt4(*(const float4*)(vp + u * 4));
            }
        }
        __syncthreads();

        float acc[2][8][4];
#pragma unroll
        for (int mt = 0; mt < 2; mt++)
#pragma unroll
            for (int g = 0; g < 8; g++)
#pragma unroll
                for (int j = 0; j < 4; j++) acc[mt][g][j] = 0.f;

#pragma unroll
        for (int kc = 0; kc < 8; kc++) {
#pragma unroll
            for (int g = 0; g < 8; g++) {
                const float* kpK = sm + KOF + (g * 8 + gid) * FSTQ + kc * 8 + tig;
                uint32_t b0 = __float_as_uint(kpK[0]);
                uint32_t b1 = __float_as_uint(kpK[4]);
                MMA_TF32(acc[0][g], aq[0][kc], b0, b1);
                MMA_TF32(acc[1][g], aq[1][kc], b0, b1);
            }
        }

        bool diag = (kb >= nkb - 2);
#pragma unroll
        for (int mt = 0; mt < 2; mt++) {
            const float* f0 = ffb + (size_t)qr[mt] * T_;
            const float* f1 = f0 + 8 * T_;
#pragma unroll
            for (int g = 0; g < 8; g++) {
                int sc = s0 + 8 * g + cl;
                float2 fa = *(const float2*)(f0 + sc);
                float2 fb = *(const float2*)(f1 + sc);
                acc[mt][g][0] = acc[mt][g][0] * (0.125f * L2E) - fa.x * L2E;
                acc[mt][g][1] = acc[mt][g][1] * (0.125f * L2E) - fa.y * L2E;
                acc[mt][g][2] = acc[mt][g][2] * (0.125f * L2E) - fb.x * L2E;
                acc[mt][g][3] = acc[mt][g][3] * (0.125f * L2E) - fb.y * L2E;
                if (diag) {
                    if (sc     > qr[mt])     acc[mt][g][0] = -1e30f;
                    if (sc + 1 > qr[mt])     acc[mt][g][1] = -1e30f;
                    if (sc     > qr[mt] + 8) acc[mt][g][2] = -1e30f;
                    if (sc + 1 > qr[mt] + 8) acc[mt][g][3] = -1e30f;
                }
            }
            float mx0 = -1e30f, mx1 = -1e30f;
#pragma unroll
            for (int g = 0; g < 8; g++) {
                mx0 = fmaxf(mx0, fmaxf(acc[mt][g][0], acc[mt][g][1]));
                mx1 = fmaxf(mx1, fmaxf(acc[mt][g][2], acc[mt][g][3]));
            }
            mx0 = fmaxf(mx0, __shfl_xor_sync(0xffffffffu, mx0, 1));
            mx0 = fmaxf(mx0, __shfl_xor_sync(0xffffffffu, mx0, 2));
            mx1 = fmaxf(mx1, __shfl_xor_sync(0xffffffffu, mx1, 1));
            mx1 = fmaxf(mx1, __shfl_xor_sync(0xffffffffu, mx1, 2));
            float mn0 = fmaxf(mrow[mt][0], mx0), mn1 = fmaxf(mrow[mt][1], mx1);
            float c0 = ex2(mrow[mt][0] - mn0), c1 = ex2(mrow[mt][1] - mn1);
            mrow[mt][0] = mn0; mrow[mt][1] = mn1;

            float s0r = 0.f, s1r = 0.f;
#pragma unroll
            for (int g = 0; g < 8; g++) {
                acc[mt][g][0] = ex2(acc[mt][g][0] - mn0);
                acc[mt][g][1] = ex2(acc[mt][g][1] - mn0);
                acc[mt][g][2] = ex2(acc[mt][g][2] - mn1);
                acc[mt][g][3] = ex2(acc[mt][g][3] - mn1);
                s0r += acc[mt][g][0] + acc[mt][g][1];
                s1r += acc[mt][g][2] + acc[mt][g][3];
            }
            s0r += __shfl_xor_sync(0xffffffffu, s0r, 1);
            s0r += __shfl_xor_sync(0xffffffffu, s0r, 2);
            s1r += __shfl_xor_sync(0xffffffffu, s1r, 1);
            s1r += __shfl_xor_sync(0xffffffffu, s1r, 2);
            lrow[mt][0] = lrow[mt][0] * c0 + s0r;
            lrow[mt][1] = lrow[mt][1] * c1 + s1r;
#pragma unroll
            for (int dg = 0; dg < 8; dg++) {
                o[mt][dg][0] *= c0; o[mt][dg][1] *= c0;
                o[mt][dg][2] *= c1; o[mt][dg][3] *= c1;
            }
        }

#pragma unroll
        for (int kc = 0; kc < 8; kc++) {
            uint32_t ap0[4], ap1[4];
            {
                float x0 = __shfl_sync(0xffffffffu, acc[0][kc][0], src0);
                float x1 = __shfl_sync(0xffffffffu, acc[0][kc][1], src0);
                float y0 = __shfl_sync(0xffffffffu, acc[0][kc][0], src1);
                float y1 = __shfl_sync(0xffffffffu, acc[0][kc][1], src1);
                float z0 = __shfl_sync(0xffffffffu, acc[0][kc][2], src0);
                float z1 = __shfl_sync(0xffffffffu, acc[0][kc][3], src0);
                float u0 = __shfl_sync(0xffffffffu, acc[0][kc][2], src1);
                float u1 = __shfl_sync(0xffffffffu, acc[0][kc][3], src1);
                ap0[0] = tf32r(od ? x1 : x0);
                ap0[1] = tf32r(od ? z1 : z0);
                ap0[2] = tf32r(od ? y1 : y0);
                ap0[3] = tf32r(od ? u1 : u0);
            }
            {
                float x0 = __shfl_sync(0xffffffffu, acc[1][kc][0], src0);
                float x1 = __shfl_sync(0xffffffffu, acc[1][kc][1], src0);
                float y0 = __shfl_sync(0xffffffffu, acc[1][kc][0], src1);
                float y1 = __shfl_sync(0xffffffffu, acc[1][kc][1], src1);
                float z0 = __shfl_sync(0xffffffffu, acc[1][kc][2], src0);
                float z1 = __shfl_sync(0xffffffffu, acc[1][kc][3], src0);
                float u0 = __shfl_sync(0xffffffffu, acc[1][kc][2], src1);
                float u1 = __shfl_sync(0xffffffffu, acc[1][kc][3], src1);
                ap1[0] = tf32r(od ? x1 : x0);
                ap1[1] = tf32r(od ? z1 : z0);
                ap1[2] = tf32r(od ? y1 : y0);
                ap1[3] = tf32r(od ? u1 : u0);
            }
#pragma unroll
            for (int dg = 0; dg < 8; dg++) {
                const float* vr = sm + VOF + (kc * 8 + tig) * FSTV + dg * 8 + gid;
                uint32_t b0 = __float_as_uint(vr[0]);
                uint32_t b1 = __float_as_uint(vr[4 * FSTV]);
                MMA_TF32(o[0][dg], ap0, b0, b1);
                MMA_TF32(o[1][dg], ap1, b0, b1);
            }
        }
    }

#pragma unroll
    for (int mt = 0; mt < 2; mt++) {
        float i0 = frcp(lrow[mt][0]), i1 = frcp(lrow[mt][1]);
        float* yb = Y + (size_t)(b * T_ + qr[mt]) * HD_ + h * D_;
#pragma unroll
        for (int dg = 0; dg < 8; dg++) {
            int dc = 8 * dg + cl;
            float2 w0 = make_float2(o[mt][dg][0] * i0, o[mt][dg][1] * i0);
            float2 w1 = make_float2(o[mt][dg][2] * i1, o[mt][dg][3] * i1);
            *(float2*)(yb + dc) = w0;
            *(float2*)(yb + 8 * (size_t)HD_ + dc) = w1;
        }
    }
}

// ---------------------------------------------------------------------------
extern "C" void kernel_launch(void* const* d_in, const int* in_sizes, int n_in,
                              void* d_out, int out_size)
{
    const float* x      = (const float*)d_in[0];
    const float* W_attn = (const float*)d_in[1];
    const float* b_attn = (const float*)d_in[2];
    const float* W_proj = (const float*)d_in[3];
    const float* b_proj = (const float*)d_in[4];

    float* out   = (float*)d_out;
    float* y_out = out;
    float* m_out = out + (size_t)B_ * T_ * C_;

    float *qkv, *ff, *att;
    cudaGetSymbolAddress((void**)&qkv, g_qkv);
    cudaGetSymbolAddress((void**)&ff,  g_ff);
    cudaGetSymbolAddress((void**)&att, g_att);

    dim3 blk(256);

    // 0) fused QKV GEMM (bulk tf32 + exact patch)
    qkv_fused<<<dim3(W3_ / 128 + 2, (B_ * T_) / 128), blk>>>(
        x, W_attn, b_attn, qkv, B_ * T_, W3_, C_);

    // 1) scores + cumsum pass1 (fused)
    scores_csum<<<dim3(T_ / 64, T_ / 64, B_), blk>>>(qkv, ff);

    // 2) cumsum pass2
    cumsum_pass2<<<dim3(T_ / 256, B_, CH_), blk>>>(ff);

    // 3) flash attention  <- lands on ncu's captured launch index
    cudaFuncSetAttribute(flash_tf32,
                         cudaFuncAttributeMaxDynamicSharedMemorySize, FSMEM);
    flash_tf32<<<dim3(T_ / 128, B_ * H_), dim3(128), FSMEM>>>(qkv, ff, att);

    // 4) FF_sum rows
    ffsum_kernel<<<dim3(T_, B_), blk>>>(ff);

    // 5) M output
    m_kernel<<<dim3((unsigned)(((size_t)B_ * T_ * T_) / 1024)), blk>>>(m_out);

    // 6) output projection
    sgemm_tf32<<<dim3(C_ / 128, (B_ * T_) / 128), blk>>>(
        att, W_proj, b_proj, y_out, B_ * T_, C_, HD_);
}

// round 11
// speedup vs baseline: 1.0808x; 1.0808x over previous
#include <cuda_runtime.h>
#include <cuda_bf16.h>
#include <cstdint>

#define B_  2
#define T_  2048
#define C_  768
#define H_  12
#define D_  64
#define HD_ 768
#define W3_ 2304   // 3*HD
#define CH_ 64
#define CL_ (T_/CH_)   // 32

typedef unsigned long long u64;

// ---- packed f32x2 helpers -------------------------------------------------
__device__ __forceinline__ u64 pk2(float lo, float hi) {
    u64 r; asm("mov.b64 %0,{%1,%2};" : "=l"(r) : "f"(lo), "f"(hi)); return r;
}
__device__ __forceinline__ u64 dup2(float v) { return pk2(v, v); }
__device__ __forceinline__ float2 up2(u64 v) {
    float2 r; asm("mov.b64 {%0,%1},%2;" : "=f"(r.x), "=f"(r.y) : "l"(v)); return r;
}
__device__ __forceinline__ void fma2(u64& d, u64 a, u64 b) {
    asm("fma.rn.f32x2 %0,%1,%2,%3;" : "=l"(d) : "l"(a), "l"(b), "l"(d));
}

// ---- tf32 / fast-math helpers ----------------------------------------------
__device__ __forceinline__ uint32_t tf32r(float x) {
    uint32_t r; asm("cvt.rna.tf32.f32 %0,%1;" : "=r"(r) : "f"(x)); return r;
}
__device__ __forceinline__ float ex2(float x) {
    float r; asm("ex2.approx.ftz.f32 %0,%1;" : "=f"(r) : "f"(x)); return r;
}
__device__ __forceinline__ float frcp(float x) {
    float r; asm("rcp.approx.ftz.f32 %0,%1;" : "=f"(r) : "f"(x)); return r;
}
#define MMA_TF32(c,a,b0,b1) \
    asm volatile("mma.sync.aligned.m16n8k8.row.col.f32.tf32.tf32.f32 " \
        "{%0,%1,%2,%3},{%4,%5,%6,%7},{%8,%9},{%0,%1,%2,%3};" \
        : "+f"((c)[0]),"+f"((c)[1]),"+f"((c)[2]),"+f"((c)[3]) \
        : "r"((a)[0]),"r"((a)[1]),"r"((a)[2]),"r"((a)[3]),"r"(b0),"r"(b1))

// Scratch
__device__ float g_qkv[(size_t)B_ * T_ * W3_];
__device__ float g_ff [(size_t)B_ * T_ * T_];
__device__ float g_ffsum[B_ * T_];
__device__ float g_att[(size_t)B_ * T_ * HD_];
__device__ float g_csum[B_ * CH_ * T_];

// ---------------------------------------------------------------------------
// Fused QKV GEMM: bulk tf32 tiles (grid.x < 18) + exact fp32 patch blocks
// (grid.x 18..21) — ONE 64-row sub-tile per patch block (de-serialized).
// ---------------------------------------------------------------------------
#define AST 20
#define BST 136
__global__ __launch_bounds__(256) void qkv_fused(
    const float* __restrict__ A, const float* __restrict__ Bm,
    const float* __restrict__ bias, float* __restrict__ Cm,
    int M, int N, int K)
{
    __shared__ float As[128 * AST];
    __shared__ float Bs[16 * BST];
    int tid = threadIdx.x, lane = tid & 31, w = tid >> 5;

    if (blockIdx.x >= (unsigned)(N / 128)) {
        // ---------------- exact fp32 patch (head-0 q,k columns) ----------
        float (*pAs)[68] = (float(*)[68])As;
        float (*pBs)[68] = (float(*)[68])Bs;
        int tx = tid & 15, ty = tid >> 4;
        int pidx = blockIdx.x - N / 128;              // 0..3
        int colbase = (pidx & 1) * 768;               // 0 or 768
        int row0 = blockIdx.y * 128 + (pidx >> 1) * 64;
        int arow = tid >> 2, acol = (tid & 3) * 4;
        int brow = tid >> 4, bcol = (tid & 15) * 4;

        const float* Ap = A + (size_t)(row0 + arow) * K + acol;
        const float* Bp = Bm + (size_t)brow * N + colbase + bcol;

        u64 acc[4][2];
#pragma unroll
        for (int i = 0; i < 4; i++) { acc[i][0] = 0ull; acc[i][1] = 0ull; }

        for (int k0 = 0; k0 < K; k0 += 16) {
            float4 a = *(const float4*)(Ap + k0);
            float4 b = *(const float4*)(Bp + (size_t)k0 * N);
            __syncthreads();
            pAs[acol + 0][arow] = a.x; pAs[acol + 1][arow] = a.y;
            pAs[acol + 2][arow] = a.z; pAs[acol + 3][arow] = a.w;
            *(float4*)&pBs[brow][bcol] = b;
            __syncthreads();
#pragma unroll
            for (int kk = 0; kk < 16; kk++) {
                float4 av = *(const float4*)&pAs[kk][ty * 4];
                u64 ad[4];
                ad[0] = dup2(av.x); ad[1] = dup2(av.y);
                ad[2] = dup2(av.z); ad[3] = dup2(av.w);
                u64 bx0 = *(const u64*)&pBs[kk][tx * 4];
                u64 bx1 = *(const u64*)&pBs[kk][tx * 4 + 2];
#pragma unroll
                for (int i = 0; i < 4; i++) {
                    fma2(acc[i][0], ad[i], bx0);
                    fma2(acc[i][1], ad[i], bx1);
                }
            }
        }
#pragma unroll
        for (int i = 0; i < 4; i++) {
            int r = row0 + ty * 4 + i;
            int cc = colbase + tx * 4;
            float2 p0 = up2(acc[i][0]);
            float2 p1 = up2(acc[i][1]);
            float4 o;
            o.x = p0.x + bias[cc + 0];
            o.y = p0.y + bias[cc + 1];
            o.z = p1.x + bias[cc + 2];
            o.w = p1.y + bias[cc + 3];
            *(float4*)&Cm[(size_t)r * N + cc] = o;
        }
        return;
    }

    // ---------------- bulk tf32 tensor-core GEMM -------------------------
    int gid = lane >> 2, tig = lane & 3;
    int row0 = blockIdx.y * 128, col0 = blockIdx.x * 128;

    int arow = tid >> 1, acol = (tid & 1) * 8;
    int brow = tid >> 4, bcol = (tid & 15) * 8;
    const float* Ap = A + (size_t)(row0 + arow) * K + acol;
    const float* Bp = Bm + (size_t)brow * N + col0 + bcol;

    float c[16][4];
#pragma unroll
    for (int g = 0; g < 16; g++)
#pragma unroll
        for (int j = 0; j < 4; j++) c[g][j] = 0.f;

    float4 a0 = *(const float4*)(Ap);
    float4 a1 = *(const float4*)(Ap + 4);
    float4 b0 = *(const float4*)(Bp);
    float4 b1 = *(const float4*)(Bp + 4);

    for (int k0 = 0; k0 < K; k0 += 16) {
        __syncthreads();
        {
            float* ad = As + arow * AST + acol;
            ad[0] = __uint_as_float(tf32r(a0.x));
            ad[1] = __uint_as_float(tf32r(a0.y));
            ad[2] = __uint_as_float(tf32r(a0.z));
            ad[3] = __uint_as_float(tf32r(a0.w));
            ad[4] = __uint_as_float(tf32r(a1.x));
            ad[5] = __uint_as_float(tf32r(a1.y));
            ad[6] = __uint_as_float(tf32r(a1.z));
            ad[7] = __uint_as_float(tf32r(a1.w));
            float* bd = Bs + brow * BST + bcol;
            bd[0] = __uint_as_float(tf32r(b0.x));
            bd[1] = __uint_as_float(tf32r(b0.y));
            bd[2] = __uint_as_float(tf32r(b0.z));
            bd[3] = __uint_as_float(tf32r(b0.w));
            bd[4] = __uint_as_float(tf32r(b1.x));
            bd[5] = __uint_as_float(tf32r(b1.y));
            bd[6] = __uint_as_float(tf32r(b1.z));
            bd[7] = __uint_as_float(tf32r(b1.w));
        }
        __syncthreads();
        if (k0 + 16 < K) {
            a0 = *(const float4*)(Ap + k0 + 16);
            a1 = *(const float4*)(Ap + k0 + 20);
            b0 = *(const float4*)(Bp + (size_t)(k0 + 16) * N);
            b1 = *(const float4*)(Bp + (size_t)(k0 + 16) * N + 4);
        }
#pragma unroll
        for (int kc = 0; kc < 2; kc++) {
            uint32_t af[4];
            const float* ab = As + (16 * w + gid) * AST + kc * 8 + tig;
            af[0] = __float_as_uint(ab[0]);
            af[1] = __float_as_uint(ab[8 * AST]);
            af[2] = __float_as_uint(ab[4]);
            af[3] = __float_as_uint(ab[8 * AST + 4]);
            const float* bb = Bs + (kc * 8 + tig) * BST + gid;
#pragma unroll
            for (int g = 0; g < 16; g++) {
                uint32_t bf0 = __float_as_uint(bb[g * 8]);
                uint32_t bf1 = __float_as_uint(bb[4 * BST + g * 8]);
                MMA_TF32(c[g], af, bf0, bf1);
            }
        }
    }

    int crow = row0 + 16 * w + gid;
#pragma unroll
    for (int g = 0; g < 16; g++) {
        int cc = col0 + g * 8 + 2 * tig;
        bool skip = (cc < 64) || (cc >= 768 && cc < 832);
        if (skip) continue;
        float bx0 = bias[cc], bx1 = bias[cc + 1];
        float2 w0 = make_float2(c[g][0] + bx0, c[g][1] + bx1);
        float2 w1 = make_float2(c[g][2] + bx0, c[g][3] + bx1);
        *(float2*)&Cm[(size_t)crow * N + cc] = w0;
        *(float2*)&Cm[(size_t)(crow + 8) * N + cc] = w1;
    }
}

// ---------------------------------------------------------------------------
// Plain tf32 GEMM (proj).
// ---------------------------------------------------------------------------
__global__ __launch_bounds__(256) void sgemm_tf32(
    const float* __restrict__ A, const float* __restrict__ Bm,
    const float* __restrict__ bias, float* __restrict__ Cm,
    int M, int N, int K)
{
    __shared__ float As[128 * AST];
    __shared__ float Bs[16 * BST];
    int tid = threadIdx.x, lane = tid & 31, w = tid >> 5;
    int gid = lane >> 2, tig = lane & 3;
    int row0 = blockIdx.y * 128, col0 = blockIdx.x * 128;

    int arow = tid >> 1, acol = (tid & 1) * 8;
    int brow = tid >> 4, bcol = (tid & 15) * 8;
    const float* Ap = A + (size_t)(row0 + arow) * K + acol;
    const float* Bp = Bm + (size_t)brow * N + col0 + bcol;

    float c[16][4];
#pragma unroll
    for (int g = 0; g < 16; g++)
#pragma unroll
        for (int j = 0; j < 4; j++) c[g][j] = 0.f;

    float4 a0 = *(const float4*)(Ap);
    float4 a1 = *(const float4*)(Ap + 4);
    float4 b0 = *(const float4*)(Bp);
    float4 b1 = *(const float4*)(Bp + 4);

    for (int k0 = 0; k0 < K; k0 += 16) {
        __syncthreads();
        {
            float* ad = As + arow * AST + acol;
            ad[0] = __uint_as_float(tf32r(a0.x));
            ad[1] = __uint_as_float(tf32r(a0.y));
            ad[2] = __uint_as_float(tf32r(a0.z));
            ad[3] = __uint_as_float(tf32r(a0.w));
            ad[4] = __uint_as_float(tf32r(a1.x));
            ad[5] = __uint_as_float(tf32r(a1.y));
            ad[6] = __uint_as_float(tf32r(a1.z));
            ad[7] = __uint_as_float(tf32r(a1.w));
            float* bd = Bs + brow * BST + bcol;
            bd[0] = __uint_as_float(tf32r(b0.x));
            bd[1] = __uint_as_float(tf32r(b0.y));
            bd[2] = __uint_as_float(tf32r(b0.z));
            bd[3] = __uint_as_float(tf32r(b0.w));
            bd[4] = __uint_as_float(tf32r(b1.x));
            bd[5] = __uint_as_float(tf32r(b1.y));
            bd[6] = __uint_as_float(tf32r(b1.z));
            bd[7] = __uint_as_float(tf32r(b1.w));
        }
        __syncthreads();
        if (k0 + 16 < K) {
            a0 = *(const float4*)(Ap + k0 + 16);
            a1 = *(const float4*)(Ap + k0 + 20);
            b0 = *(const float4*)(Bp + (size_t)(k0 + 16) * N);
            b1 = *(const float4*)(Bp + (size_t)(k0 + 16) * N + 4);
        }
#pragma unroll
        for (int kc = 0; kc < 2; kc++) {
            uint32_t af[4];
            const float* ab = As + (16 * w + gid) * AST + kc * 8 + tig;
            af[0] = __float_as_uint(ab[0]);
            af[1] = __float_as_uint(ab[8 * AST]);
            af[2] = __float_as_uint(ab[4]);
            af[3] = __float_as_uint(ab[8 * AST + 4]);
            const float* bb = Bs + (kc * 8 + tig) * BST + gid;
#pragma unroll
            for (int g = 0; g < 16; g++) {
                uint32_t bf0 = __float_as_uint(bb[g * 8]);
                uint32_t bf1 = __float_as_uint(bb[4 * BST + g * 8]);
                MMA_TF32(c[g], af, bf0, bf1);
            }
        }
    }

    int crow = row0 + 16 * w + gid;
#pragma unroll
    for (int g = 0; g < 16; g++) {
        int cc = col0 + g * 8 + 2 * tig;
        float bx0 = bias[cc], bx1 = bias[cc + 1];
        float2 w0 = make_float2(c[g][0] + bx0, c[g][1] + bx1);
        float2 w1 = make_float2(c[g][2] + bx0, c[g][3] + bx1);
        *(float2*)&Cm[(size_t)crow * N + cc] = w0;
        *(float2*)&Cm[(size_t)(crow + 8) * N + cc] = w1;
    }
}

// ---------------------------------------------------------------------------
// Head-0 scores fused with cumsum pass1 (unchanged from R10).
// ---------------------------------------------------------------------------
__global__ __launch_bounds__(256) void scores_csum(
    const float* __restrict__ qkv, float* __restrict__ S)
{
    int b = blockIdx.z, tb = blockIdx.y, sb = blockIdx.x;
    int t0 = tb * 64, s0 = sb * 64;
    if (s0 > t0) return;
    int tid = threadIdx.x, tx = tid & 15, ty = tid >> 4;
    float* Sb = S + (size_t)b * T_ * T_;

    __shared__ float Qs[64][68];
    __shared__ float Ks[64][68];
    __shared__ float red[64][17];
    const float* qb = qkv + ((size_t)b * T_ + t0) * W3_;
    const float* kb = qkv + ((size_t)b * T_ + s0) * W3_ + HD_;
    int lr = tid >> 4, lc = (tid & 15) * 4;
#pragma unroll
    for (int g = 0; g < 4; g++) {
        int r = lr + g * 16;
        *(float4*)&Qs[r][lc] = *(const float4*)&qb[(size_t)r * W3_ + lc];
        *(float4*)&Ks[r][lc] = *(const float4*)&kb[(size_t)r * W3_ + lc];
    }
    __syncthreads();

    float acc[4][4] = {};
#pragma unroll
    for (int dk = 0; dk < 16; dk++) {
        float4 qv[4], kv[4];
#pragma unroll
        for (int i = 0; i < 4; i++) qv[i] = *(const float4*)&Qs[ty * 4 + i][dk * 4];
#pragma unroll
        for (int j = 0; j < 4; j++) kv[j] = *(const float4*)&Ks[tx * 4 + j][dk * 4];
#pragma unroll
        for (int i = 0; i < 4; i++)
#pragma unroll
            for (int j = 0; j < 4; j++)
                acc[i][j] += qv[i].x * kv[j].x + qv[i].y * kv[j].y
                           + qv[i].z * kv[j].z + qv[i].w * kv[j].w;
    }

    float colsum[4] = {0.f, 0.f, 0.f, 0.f};
#pragma unroll
    for (int i = 0; i < 4; i++) {
        int t = t0 + ty * 4 + i;
        float out[4];
#pragma unroll
        for (int j = 0; j < 4; j++) {
            int s = s0 + tx * 4 + j;
            float v = acc[i][j] * 0.125f;
            out[j] = (s < t && s > 0) ? fmaxf(v, 0.f) : 0.f;
            colsum[j] += out[j];
        }
        *(float4*)&Sb[(size_t)t * T_ + s0 + tx * 4] = *(float4*)out;
    }
#pragma unroll
    for (int j = 0; j < 4; j++) red[tx * 4 + j][ty] = colsum[j];
    __syncthreads();

    if (tid < 128) {
        int col = tid & 63, half = tid >> 6;
        float s = 0.f;
#pragma unroll
        for (int k = 0; k < 8; k++) s += red[col][half * 8 + k];
        int chunk = tb * 2 + half;
        g_csum[(b * CH_ + chunk) * T_ + s0 + col] = s;
    }
}

// ---------------------------------------------------------------------------
__global__ __launch_bounds__(256) void cumsum_pass2(float* __restrict__ S)
{
    int b = blockIdx.y, chunk = blockIdx.z;
    int c0 = chunk * CL_;
    int s0 = blockIdx.x * 256;
    if (s0 >= c0 + CL_) return;
    int s = s0 + threadIdx.x;
    float base = 0.f;
    for (int c = 0; c < chunk; c++) base += g_csum[(b * CH_ + c) * T_ + s];
    float* p = S + (size_t)b * T_ * T_ + (size_t)c0 * T_ + s;
    float acc = base;
#pragma unroll 8
    for (int t = 0; t < CL_; t++) {
        float v = p[(size_t)t * T_];
        p[(size_t)t * T_] = acc;
        acc += (c0 + t > s) ? v : 0.f;
    }
}

// ---------------------------------------------------------------------------
__global__ __launch_bounds__(256) void ffsum_kernel(const float* __restrict__ FF)
{
    int b = blockIdx.y, t = blockIdx.x;
    const float4* row = (const float4*)(FF + ((size_t)b * T_ + t) * T_);
    int n4 = (t >> 2) + 1;
    float s = 0.f;
    for (int j = threadIdx.x; j < n4; j += 256) {
        float4 v = row[j];
        int sb = j * 4;
        s += (sb     <= t ? fminf(v.x, 1.f) : 0.f)
           + (sb + 1 <= t ? fminf(v.y, 1.f) : 0.f)
           + (sb + 2 <= t ? fminf(v.z, 1.f) : 0.f)
           + (sb + 3 <= t ? fminf(v.w, 1.f) : 0.f);
    }
#pragma unroll
    for (int off = 16; off; off >>= 1) s += __shfl_xor_sync(0xffffffffu, s, off);
    __shared__ float red[8];
    int lane = threadIdx.x & 31, w = threadIdx.x >> 5;
    if (lane == 0) red[w] = s;
    __syncthreads();
    if (w == 0) {
        s = (lane < 8) ? red[lane] : 0.f;
#pragma unroll
        for (int off = 4; off; off >>= 1) s += __shfl_xor_sync(0xffffffffu, s, off);
        if (lane == 0) g_ffsum[b * T_ + t] = s;
    }
}

__global__ __launch_bounds__(256) void m_kernel(float* __restrict__ Mout)
{
    size_t idx4 = (size_t)blockIdx.x * 256 + threadIdx.x;
    size_t idx = idx4 * 4;
    int j = (int)(idx % T_);
    size_t r = idx / T_;
    int i = (int)(r % T_);
    int b = (int)(r / T_);
    float4 fs = *(const float4*)&g_ffsum[b * T_ + j];
    float fi = (float)i;
    float4 o = make_float4(fi - fs.x, fi - fs.y, fi - fs.z, fi - fs.w);
    *(float4*)&Mout[idx] = o;
}

// ---------------------------------------------------------------------------
// Flash attention v4 — occupancy-first: 256 threads / 8 warps, each warp owns
// 16 q-rows (acc[8][4]+o[8][4] = 64 persistent regs; Q frags reloaded per kc).
// __launch_bounds__(256,2) -> <=128 regs -> 2 blocks x 8 warps = 16 warps/SM.
// Numerics identical to R8 (same ops per row, same order).
// ---------------------------------------------------------------------------
#define FSTQ 68
#define FSTV 72
#define QOF 0
#define KOF (128 * FSTQ)
#define VOF (KOF + 64 * FSTQ)
#define FSMEM ((128 * FSTQ + 64 * FSTQ + 64 * FSTV) * 4)   // 70656 B
#define L2E 1.44269504f

__device__ __forceinline__ uint4 cvt4(float4 v) {
    uint4 r;
    r.x = tf32r(v.x); r.y = tf32r(v.y); r.z = tf32r(v.z); r.w = tf32r(v.w);
    return r;
}

__global__ __launch_bounds__(256, 2) void flash_tf32(
    const float* __restrict__ qkv, const float* __restrict__ FF,
    float* __restrict__ Y)
{
    extern __shared__ __align__(16) float sm[];

    int tid = threadIdx.x;
    int lane = tid & 31, w = tid >> 5;          // 8 warps
    int gid = lane >> 2, tig = lane & 3;
    int tb = gridDim.x - 1 - blockIdx.x;        // big tiles first
    int bh = blockIdx.y;
    int b = bh / H_, h = bh % H_;
    int t0 = tb * 128;

    const float* kvb = qkv + (size_t)b * T_ * W3_;

    // ---- load Q tile (128 rows x 64): half row per thread ----
    {
        int r = tid >> 1, c0 = (tid & 1) * 32;
        const float* qp = kvb + (size_t)(t0 + r) * W3_ + h * D_ + c0;
        uint4* dst = (uint4*)(sm + QOF + r * FSTQ + c0);
#pragma unroll
        for (int u = 0; u < 8; u++)
            dst[u] = cvt4(*(const float4*)(qp + u * 4));
    }
    __syncthreads();

    float m0 = -1e30f, m1 = -1e30f, l0 = 0.f, l1 = 0.f;
    float o[8][4];
#pragma unroll
    for (int dg = 0; dg < 8; dg++)
#pragma unroll
        for (int j = 0; j < 4; j++) o[dg][j] = 0.f;

    int qr0 = t0 + 16 * w + gid;                // warp's rows: qr0, qr0+8
    const float* f0p = FF + (size_t)b * T_ * T_ + (size_t)qr0 * T_;
    const float* f1p = f0p + 8 * T_;
    int cl = tig << 1;
    int src0 = (lane & ~3) | (tig >> 1);
    int src1 = src0 + 2;
    bool od = (tig & 1);
    const float* qbase = sm + QOF + (16 * w + gid) * FSTQ + tig;

    int nkb = 2 * tb + 2;
    for (int kb = 0; kb < nkb; kb++) {
        int s0 = kb * 64;
        __syncthreads();
        // ---- load K,V tiles (64 x 64 each): quarter row per thread ----
        {
            int r = tid >> 2, c0 = (tid & 3) * 16;
            const float* kp = kvb + (size_t)(s0 + r) * W3_ + HD_     + h * D_ + c0;
            const float* vp = kvb + (size_t)(s0 + r) * W3_ + 2 * HD_ + h * D_ + c0;
            uint4* dk = (uint4*)(sm + KOF + r * FSTQ + c0);
            uint4* dv = (uint4*)(sm + VOF + r * FSTV + c0);
#pragma unroll
            for (int u = 0; u < 4; u++) {
                dk[u] = cvt4(*(const float4*)(kp + u * 4));
                dv[u] = cvt4(*(const float4*)(vp + u * 4));
            }
        }
        __syncthreads();

        // ---- QK^T: 8 n8-tiles; Q frags reloaded per k-chunk ----
        float acc[8][4];
#pragma unroll
        for (int g = 0; g < 8; g++)
#pragma unroll
            for (int j = 0; j < 4; j++) acc[g][j] = 0.f;

#pragma unroll
        for (int kc = 0; kc < 8; kc++) {
            uint32_t aq[4];
            const float* q0 = qbase + kc * 8;
            aq[0] = __float_as_uint(q0[0]);
            aq[1] = __float_as_uint(q0[8 * FSTQ]);
            aq[2] = __float_as_uint(q0[4]);
            aq[3] = __float_as_uint(q0[8 * FSTQ + 4]);
#pragma unroll
            for (int g = 0; g < 8; g++) {
                const float* kpK = sm + KOF + (g * 8 + gid) * FSTQ + kc * 8 + tig;
                uint32_t b0 = __float_as_uint(kpK[0]);
                uint32_t b1 = __float_as_uint(kpK[4]);
                MMA_TF32(acc[g], aq, b0, b1);
            }
        }

        // ---- logits (log2 domain), FF subtract, causal mask, softmax ----
        bool diag = (kb >= nkb - 2);
#pragma unroll
        for (int g = 0; g < 8; g++) {
            int sc = s0 + 8 * g + cl;
            float2 fa = *(const float2*)(f0p + sc);
            float2 fb = *(const float2*)(f1p + sc);
            acc[g][0] = acc[g][0] * (0.125f * L2E) - fa.x * L2E;
            acc[g][1] = acc[g][1] * (0.125f * L2E) - fa.y * L2E;
            acc[g][2] = acc[g][2] * (0.125f * L2E) - fb.x * L2E;
            acc[g][3] = acc[g][3] * (0.125f * L2E) - fb.y * L2E;
            if (diag) {
                if (sc     > qr0)     acc[g][0] = -1e30f;
                if (sc + 1 > qr0)     acc[g][1] = -1e30f;
                if (sc     > qr0 + 8) acc[g][2] = -1e30f;
                if (sc + 1 > qr0 + 8) acc[g][3] = -1e30f;
            }
        }
        float mx0 = -1e30f, mx1 = -1e30f;
#pragma unroll
        for (int g = 0; g < 8; g++) {
            mx0 = fmaxf(mx0, fmaxf(acc[g][0], acc[g][1]));
            mx1 = fmaxf(mx1, fmaxf(acc[g][2], acc[g][3]));
        }
        mx0 = fmaxf(mx0, __shfl_xor_sync(0xffffffffu, mx0, 1));
        mx0 = fmaxf(mx0, __shfl_xor_sync(0xffffffffu, mx0, 2));
        mx1 = fmaxf(mx1, __shfl_xor_sync(0xffffffffu, mx1, 1));
        mx1 = fmaxf(mx1, __shfl_xor_sync(0xffffffffu, mx1, 2));
        float mn0 = fmaxf(m0, mx0), mn1 = fmaxf(m1, mx1);
        float c0_ = ex2(m0 - mn0), c1_ = ex2(m1 - mn1);
        m0 = mn0; m1 = mn1;

        float s0r = 0.f, s1r = 0.f;
#pragma unroll
        for (int g = 0; g < 8; g++) {
            acc[g][0] = ex2(acc[g][0] - mn0);
            acc[g][1] = ex2(acc[g][1] - mn0);
            acc[g][2] = ex2(acc[g][2] - mn1);
            acc[g][3] = ex2(acc[g][3] - mn1);
            s0r += acc[g][0] + acc[g][1];
            s1r += acc[g][2] + acc[g][3];
        }
        s0r += __shfl_xor_sync(0xffffffffu, s0r, 1);
        s0r += __shfl_xor_sync(0xffffffffu, s0r, 2);
        s1r += __shfl_xor_sync(0xffffffffu, s1r, 1);
        s1r += __shfl_xor_sync(0xffffffffu, s1r, 2);
        l0 = l0 * c0_ + s0r;
        l1 = l1 * c1_ + s1r;
#pragma unroll
        for (int dg = 0; dg < 8; dg++) {
            o[dg][0] *= c0_; o[dg][1] *= c0_;
            o[dg][2] *= c1_; o[dg][3] *= c1_;
        }

        // ---- PV: P fragments via warp shuffles ----
#pragma unroll
        for (int kc = 0; kc < 8; kc++) {
            uint32_t ap[4];
            {
                float x0 = __shfl_sync(0xffffffffu, acc[kc][0], src0);
                float x1 = __shfl_sync(0xffffffffu, acc[kc][1], src0);
                float y0 = __shfl_sync(0xffffffffu, acc[kc][0], src1);
                float y1 = __shfl_sync(0xffffffffu, acc[kc][1], src1);
                float z0 = __shfl_sync(0xffffffffu, acc[kc][2], src0);
                float z1 = __shfl_sync(0xffffffffu, acc[kc][3], src0);
                float u0 = __shfl_sync(0xffffffffu, acc[kc][2], src1);
                float u1 = __shfl_sync(0xffffffffu, acc[kc][3], src1);
                ap[0] = tf32r(od ? x1 : x0);
                ap[1] = tf32r(od ? z1 : z0);
                ap[2] = tf32r(od ? y1 : y0);
                ap[3] = tf32r(od ? u1 : u0);
            }
#pragma unroll
            for (int dg = 0; dg < 8; dg++) {
                const float* vr = sm + VOF + (kc * 8 + tig) * FSTV + dg * 8 + gid;
                uint32_t b0 = __float_as_uint(vr[0]);
                uint32_t b1 = __float_as_uint(vr[4 * FSTV]);
                MMA_TF32(o[dg], ap, b0, b1);
            }
        }
    }

    // ---- write y (rows qr0, qr0+8) ----
    float i0 = frcp(l0), i1 = frcp(l1);
    float* yb = Y + (size_t)(b * T_ + qr0) * HD_ + h * D_;
#pragma unroll
    for (int dg = 0; dg < 8; dg++) {
        int dc = 8 * dg + cl;
        float2 w0 = make_float2(o[dg][0] * i0, o[dg][1] * i0);
        float2 w1 = make_float2(o[dg][2] * i1, o[dg][3] * i1);
        *(float2*)(yb + dc) = w0;
        *(float2*)(yb + 8 * (size_t)HD_ + dc) = w1;
    }
}

// ---------------------------------------------------------------------------
extern "C" void kernel_launch(void* const* d_in, const int* in_sizes, int n_in,
                              void* d_out, int out_size)
{
    const float* x      = (const float*)d_in[0];
    const float* W_attn = (const float*)d_in[1];
    const float* b_attn = (const float*)d_in[2];
    const float* W_proj = (const float*)d_in[3];
    const float* b_proj = (const float*)d_in[4];

    float* out   = (float*)d_out;
    float* y_out = out;
    float* m_out = out + (size_t)B_ * T_ * C_;

    float *qkv, *ff, *att;
    cudaGetSymbolAddress((void**)&qkv, g_qkv);
    cudaGetSymbolAddress((void**)&ff,  g_ff);
    cudaGetSymbolAddress((void**)&att, g_att);

    dim3 blk(256);

    // 0) fused QKV GEMM (bulk tf32 + 4 parallel exact patch blocks)
    qkv_fused<<<dim3(W3_ / 128 + 4, (B_ * T_) / 128), blk>>>(
        x, W_attn, b_attn, qkv, B_ * T_, W3_, C_);

    // 1) scores + cumsum pass1 (fused)
    scores_csum<<<dim3(T_ / 64, T_ / 64, B_), blk>>>(qkv, ff);

    // 2) cumsum pass2
    cumsum_pass2<<<dim3(T_ / 256, B_, CH_), blk>>>(ff);

    // 3) flash attention  <- ncu's captured launch index
    cudaFuncSetAttribute(flash_tf32,
                         cudaFuncAttributeMaxDynamicSharedMemorySize, FSMEM);
    flash_tf32<<<dim3(T_ / 128, B_ * H_), dim3(256), FSMEM>>>(qkv, ff, att);

    // 4) FF_sum rows
    ffsum_kernel<<<dim3(T_, B_), blk>>>(ff);

    // 5) M output
    m_kernel<<<dim3((unsigned)(((size_t)B_ * T_ * T_) / 1024)), blk>>>(m_out);

    // 6) output projection
    sgemm_tf32<<<dim3(C_ / 128, (B_ * T_) / 128), blk>>>(
        att, W_proj, b_proj, y_out, B_ * T_, C_, HD_);
}